// round 17
// baseline (speedup 1.0000x reference)
#include <cuda_runtime.h>
#include <cuda_fp16.h>
#include <cstdint>

#define NMOL 512
#define MA   64
#define F    128
#define NF   16
#define DIN  2176   // F*(1+NF)
#define HID  512

// ======================= helpers =======================
__device__ __forceinline__ uint32_t smem_to_u32(const void* p) {
    uint32_t a;
    asm("{ .reg .u64 t; cvta.to.shared.u64 t, %1; cvt.u32.u64 %0, t; }" : "=r"(a) : "l"(p));
    return a;
}
__device__ __forceinline__ void cpasync16(uint32_t s, const void* g) {
    asm volatile("cp.async.cg.shared.global [%0], [%1], 16;" :: "r"(s), "l"(g) : "memory");
}
__device__ __forceinline__ void cp_commit() { asm volatile("cp.async.commit_group;" ::: "memory"); }
__device__ __forceinline__ void cp_wait0()  { asm volatile("cp.async.wait_group 0;"  ::: "memory"); }

__device__ __forceinline__ void ld4(uint32_t& r0, uint32_t& r1, uint32_t& r2, uint32_t& r3, uint32_t a) {
    asm volatile("ldmatrix.sync.aligned.m8n8.x4.shared.b16 {%0,%1,%2,%3}, [%4];"
                 : "=r"(r0), "=r"(r1), "=r"(r2), "=r"(r3) : "r"(a));
}
__device__ __forceinline__ void ld4t(uint32_t& r0, uint32_t& r1, uint32_t& r2, uint32_t& r3, uint32_t a) {
    asm volatile("ldmatrix.sync.aligned.m8n8.x4.trans.shared.b16 {%0,%1,%2,%3}, [%4];"
                 : "=r"(r0), "=r"(r1), "=r"(r2), "=r"(r3) : "r"(a));
}
// f16 MMA, f32 accumulate: m16n8k16
__device__ __forceinline__ void mma16(float& c0, float& c1, float& c2, float& c3,
                                      uint32_t a0, uint32_t a1, uint32_t a2, uint32_t a3,
                                      uint32_t b0, uint32_t b1) {
    asm volatile("mma.sync.aligned.m16n8k16.row.col.f32.f16.f16.f32 "
                 "{%0,%1,%2,%3}, {%4,%5,%6,%7}, {%8,%9}, {%0,%1,%2,%3};"
                 : "+f"(c0), "+f"(c1), "+f"(c2), "+f"(c3)
                 : "r"(a0), "r"(a1), "r"(a2), "r"(a3), "r"(b0), "r"(b1));
}
__device__ __forceinline__ uint32_t h2u(__half2 h) { return *(uint32_t*)&h; }

// ---------- scratch (device globals: allocation-free) ----------
__device__ __align__(256) __half g_Uh[(size_t)NMOL * MA * NF * F];   // 134 MB
__device__ __align__(256) __half g_Th[(size_t)NMOL * MA * HID];      // 32 MB
__device__ __align__(256) __half g_hh[(size_t)NMOL * MA * F];        // 8 MB
__device__ __align__(256) __half g_W1h[(size_t)DIN * HID];           // 2.2 MB  (k-major)
__device__ __align__(256) __half g_W2h[(size_t)HID * F];             // 128 KB  (k-major)

// ---------- kprep: z->float copy, r copy, f32->f16 converts, ONE launch ----------
__global__ void kprep(const int* __restrict__ z, const float* __restrict__ r,
                      const float* __restrict__ h,  const float* __restrict__ W1,
                      const float* __restrict__ W2,
                      float* __restrict__ oz, float* __restrict__ orr,
                      __half* __restrict__ hh, __half* __restrict__ W1h,
                      __half* __restrict__ W2h,
                      int nz, int nr, int nh, int ncopy)
{
    const int n1 = DIN * HID, n2 = HID * F;
    int idx = blockIdx.x * blockDim.x + threadIdx.x;
    if (idx < ncopy) {
        if (idx < nz) oz[idx] = (float)z[idx];
        else          orr[idx - nz] = r[idx - nz];
        return;
    }
    int i = (idx - ncopy) * 4;
    const float* s; __half* d; int off;
    if (i < nh)                { s = h;  d = hh;  off = 0; }
    else if (i < nh + n1)      { s = W1; d = W1h; off = nh; }
    else if (i < nh + n1 + n2) { s = W2; d = W2h; off = nh + n1; }
    else return;
    int j = i - off;
    float4 v = *(const float4*)(s + j);
    __half2 a = __floats2half2_rn(v.x, v.y);
    __half2 b = __floats2half2_rn(v.z, v.w);
    *(uint2*)(d + j) = make_uint2(h2u(a), h2u(b));
}

// ======================= K1: RBF + aggregation on tensor cores (round-12 version) =======================
__global__ __launch_bounds__(256) void k1_tc(
    const int* __restrict__ z, const float* __restrict__ r,
    const float* __restrict__ dist, const float* __restrict__ widths,
    const __half* __restrict__ hh, __half* __restrict__ U)
{
    __shared__ __half sh_h[MA * F];   // 16 KB, swizzled k-major (256B rows)
    __shared__ __half sh_w[MA * MA];  // 8 KB, swizzled row-major (128B rows)
    __shared__ float s_r[192];
    __shared__ float s_m[64];
    int n = blockIdx.x, tid = threadIdx.x;
    int wid = tid >> 5, lane = tid & 31;
    int gid = lane >> 2, tig = lane & 3;
    int warp_m = wid >> 1, warp_n = wid & 1;
    uint32_t hbase = smem_to_u32(sh_h), wbase = smem_to_u32(sh_w);

    {
        const __half* hg = hh + (size_t)n * MA * F;
#pragma unroll
        for (int p = 0; p < 4; p++) {
            int idx = p * 256 + tid;
            int row = idx >> 4, u = idx & 15;
            cpasync16(hbase + row * 256 + ((u ^ (row & 7)) << 4), hg + (size_t)row * F + u * 8);
        }
        cp_commit();
    }
    if (tid < 192) s_r[tid] = r[(size_t)n * 192 + tid];
    if (tid >= 192) s_m[tid - 192] = (z[n * MA + (tid - 192)] > -1) ? 1.0f : 0.0f;
    __syncthreads();

    float d[16];
    {
        int b = tid & 63;
        float bx = s_r[b * 3 + 0], by = s_r[b * 3 + 1], bz = s_r[b * 3 + 2];
        float mb = s_m[b];
#pragma unroll
        for (int q = 0; q < 16; q++) {
            int a = (tid >> 6) + 4 * q;
            float dx = s_r[a * 3 + 0] - bx;
            float dy = s_r[a * 3 + 1] - by;
            float dz = s_r[a * 3 + 2] - bz;
            float dd = sqrtf(dx * dx + dy * dy + dz * dz + 1e-12f);
            if (s_m[a] * mb == 0.0f) dd = 1e9f;
            d[q] = dd;
        }
    }

    int aRow = warp_m * 16 + (lane & 15);
    int aSw  = lane & 7;
    int kuHi = (lane >> 4);
    int bKrl = (lane & 7) + ((lane >> 3) & 1) * 8;
    int bNuL = (lane >> 4);
    int wb   = tid & 63;
    __half* Un = U + (size_t)n * MA * (NF * F);

    for (int f = 0; f < NF; f++) {
        float mu   = __ldg(&dist[f]);
        float isg2 = 1.4426950408889634f / __ldg(&widths[f]);
        __syncthreads();
#pragma unroll
        for (int q = 0; q < 16; q++) {
            int a = (tid >> 6) + 4 * q;
            float t = d[q] - mu;
            __half wv = __float2half_rn(5.0f * exp2f(-t * t * isg2));
            int off = a * 128 + ((((wb >> 3) ^ (a & 7))) << 4) + (wb & 7) * 2;
            *(__half*)((char*)sh_w + off) = wv;
        }
        if (f == 0) cp_wait0();
        __syncthreads();

        float acc[8][4];
#pragma unroll
        for (int nf = 0; nf < 8; nf++)
#pragma unroll
            for (int q = 0; q < 4; q++) acc[nf][q] = 0.0f;

#pragma unroll
        for (int kk = 0; kk < 4; kk++) {
            uint32_t a0, a1, a2, a3;
            uint32_t ad = wbase + aRow * 128 + (((kk * 2 + kuHi) ^ aSw) << 4);
            ld4(a0, a1, a2, a3, ad);
#pragma unroll
            for (int np = 0; np < 4; np++) {
                int krow = kk * 16 + bKrl;
                int nu = warp_n * 8 + np * 2 + bNuL;
                uint32_t bd = hbase + krow * 256 + ((nu ^ (krow & 7)) << 4);
                uint32_t b0, b1r, b2, b3;
                ld4t(b0, b1r, b2, b3, bd);
                int nf0 = np * 2, nf1 = nf0 + 1;
                mma16(acc[nf0][0], acc[nf0][1], acc[nf0][2], acc[nf0][3],
                      a0, a1, a2, a3, b0, b1r);
                mma16(acc[nf1][0], acc[nf1][1], acc[nf1][2], acc[nf1][3],
                      a0, a1, a2, a3, b2, b3);
            }
        }
        int rr = warp_m * 16 + gid;
#pragma unroll
        for (int nf = 0; nf < 8; nf++) {
            int cc = warp_n * 64 + nf * 8 + tig * 2;
            *(uint32_t*)&Un[(size_t)rr * (NF * F) + f * F + cc] =
                h2u(__floats2half2_rn(acc[nf][0], acc[nf][1]));
            *(uint32_t*)&Un[(size_t)(rr + 8) * (NF * F) + f * F + cc] =
                h2u(__floats2half2_rn(acc[nf][2], acc[nf][3]));
        }
    }
}

// ======================= K2: T = silu([h|U] @ W1 + b1)  (round-12 best config) =======================
#define K2_CHUNKS 17
#define K2_A_BYTES 32768
#define K2_B_BYTES 65536
#define K2_STAGE   (K2_A_BYTES + K2_B_BYTES)   // 98304
#define K2_DYN     (2 * K2_STAGE)              // 196608

__device__ __forceinline__ void k2_load(int j, int row0, int col0,
    const __half* __restrict__ hh, const __half* __restrict__ Uh,
    const __half* __restrict__ W1h, uint32_t sA, uint32_t sB, int tid)
{
    int k0 = j * 128;
    const __half* Ab; size_t lda;
    if (j == 0) { Ab = hh + (size_t)row0 * F;                lda = F; }
    else        { Ab = Uh + (size_t)row0 * 2048 + (k0 - F);  lda = 2048; }
#pragma unroll
    for (int p = 0; p < 4; p++) {
        int idx = p * 512 + tid;
        int m = idx >> 4, u = idx & 15;
        cpasync16(sA + m * 256 + (((u ^ (m & 7))) << 4), Ab + (size_t)m * lda + u * 8);
    }
    const __half* Bb = W1h + (size_t)k0 * HID + col0;
#pragma unroll
    for (int p = 0; p < 8; p++) {
        int idx = p * 512 + tid;
        int kr = idx >> 5, u = idx & 31;
        cpasync16(sB + kr * 512 + (((u ^ (kr & 7))) << 4), Bb + (size_t)kr * HID + u * 8);
    }
}

__global__ __launch_bounds__(512, 1) void k2_tc(
    const __half* __restrict__ hh, const __half* __restrict__ Uh,
    const __half* __restrict__ W1h, const float* __restrict__ b1,
    __half* __restrict__ T)
{
    extern __shared__ char dynsm[];
    uint32_t dbase = smem_to_u32(dynsm);
    int tid = threadIdx.x, wid = tid >> 5, lane = tid & 31;
    int gid = lane >> 2, tig = lane & 3;
    int warp_m = wid >> 2, warp_n = wid & 3;
    int col0 = blockIdx.x * 256, row0 = blockIdx.y * 128;

    float acc[2][8][4];
#pragma unroll
    for (int mf = 0; mf < 2; mf++)
#pragma unroll
        for (int nf = 0; nf < 8; nf++)
#pragma unroll
            for (int q = 0; q < 4; q++) acc[mf][nf][q] = 0.0f;

    int aRow = warp_m * 32 + (lane & 15);
    int aSw  = lane & 7;
    int kuHi = (lane >> 4);
    int bKrl = (lane & 7) + ((lane >> 3) & 1) * 8;
    int bNuL = (lane >> 4);

    k2_load(0, row0, col0, hh, Uh, W1h, dbase, dbase + K2_A_BYTES, tid);
    cp_commit();

    for (int j = 0; j < K2_CHUNKS; j++) {
        cp_wait0();
        __syncthreads();
        if (j + 1 < K2_CHUNKS) {
            uint32_t sN = dbase + ((j + 1) & 1) * K2_STAGE;
            k2_load(j + 1, row0, col0, hh, Uh, W1h, sN, sN + K2_A_BYTES, tid);
            cp_commit();
        }
        uint32_t sA = dbase + (j & 1) * K2_STAGE;
        uint32_t sB = sA + K2_A_BYTES;
#pragma unroll
        for (int kk = 0; kk < 8; kk++) {
            uint32_t a[2][4];
#pragma unroll
            for (int mf = 0; mf < 2; mf++) {
                int rowm = aRow + mf * 16;
                uint32_t ad = sA + rowm * 256 + (((kk * 2 + kuHi) ^ aSw) << 4);
                ld4(a[mf][0], a[mf][1], a[mf][2], a[mf][3], ad);
            }
#pragma unroll
            for (int np = 0; np < 4; np++) {
                int krow = kk * 16 + bKrl;
                int nu = warp_n * 8 + np * 2 + bNuL;
                uint32_t bd = sB + krow * 512 + (((nu ^ (krow & 7))) << 4);
                uint32_t b0, b1r, b2, b3;
                ld4t(b0, b1r, b2, b3, bd);
                int nf0 = np * 2, nf1 = nf0 + 1;
#pragma unroll
                for (int mf = 0; mf < 2; mf++) {
                    mma16(acc[mf][nf0][0], acc[mf][nf0][1], acc[mf][nf0][2], acc[mf][nf0][3],
                          a[mf][0], a[mf][1], a[mf][2], a[mf][3], b0, b1r);
                    mma16(acc[mf][nf1][0], acc[mf][nf1][1], acc[mf][nf1][2], acc[mf][nf1][3],
                          a[mf][0], a[mf][1], a[mf][2], a[mf][3], b2, b3);
                }
            }
        }
    }

#pragma unroll
    for (int mf = 0; mf < 2; mf++) {
        int rr = row0 + warp_m * 32 + mf * 16 + gid;
#pragma unroll
        for (int nf = 0; nf < 8; nf++) {
            int cc = col0 + warp_n * 64 + nf * 8 + tig * 2;
            float ba = __ldg(&b1[cc]), bb = __ldg(&b1[cc + 1]);
            float x0 = acc[mf][nf][0] + ba, x1 = acc[mf][nf][1] + bb;
            float x2 = acc[mf][nf][2] + ba, x3 = acc[mf][nf][3] + bb;
            x0 = x0 / (1.0f + __expf(-x0));
            x1 = x1 / (1.0f + __expf(-x1));
            x2 = x2 / (1.0f + __expf(-x2));
            x3 = x3 / (1.0f + __expf(-x3));
            *(uint32_t*)&T[(size_t)rr * HID + cc]       = h2u(__floats2half2_rn(x0, x1));
            *(uint32_t*)&T[(size_t)(rr + 8) * HID + cc] = h2u(__floats2half2_rn(x2, x3));
        }
    }
}

// ======================= K3: out = h + 0.1*(T @ W2 + b2)*mask =======================
// Restructured to k2's proven 16-warp shape: 512 threads, 4(m)x4(n), warp tile 32x32,
// BK=128, 2-stage, one barrier per chunk. Regs ~110 (was 172) -> 4 warps/SMSP.
#define K3_CHUNKS 4
#define K3_A_BYTES 32768
#define K3_B_BYTES 32768
#define K3_STAGE   (K3_A_BYTES + K3_B_BYTES)   // 65536
#define K3_DYN     (2 * K3_STAGE)              // 131072

__device__ __forceinline__ void k3_load(int j, int row0,
    const __half* __restrict__ T, const __half* __restrict__ W2h,
    uint32_t sA, uint32_t sB, int tid)
{
    int k0 = j * 128;
    const __half* Ab = T + (size_t)row0 * HID + k0;
#pragma unroll
    for (int p = 0; p < 4; p++) {
        int idx = p * 512 + tid;
        int m = idx >> 4, u = idx & 15;
        cpasync16(sA + m * 256 + (((u ^ (m & 7))) << 4), Ab + (size_t)m * HID + u * 8);
    }
    const __half* Bb = W2h + (size_t)k0 * F;
#pragma unroll
    for (int p = 0; p < 4; p++) {
        int idx = p * 512 + tid;
        int kr = idx >> 4, u = idx & 15;
        cpasync16(sB + kr * 256 + (((u ^ (kr & 7))) << 4), Bb + (size_t)kr * F + u * 8);
    }
}

__global__ __launch_bounds__(512, 1) void k3_tc(
    const __half* __restrict__ T, const __half* __restrict__ W2h,
    const float* __restrict__ b2, const float* __restrict__ h,
    const int* __restrict__ z, float* __restrict__ out)
{
    extern __shared__ char dynsm[];
    uint32_t dbase = smem_to_u32(dynsm);
    int tid = threadIdx.x, wid = tid >> 5, lane = tid & 31;
    int gid = lane >> 2, tig = lane & 3;
    int warp_m = wid >> 2, warp_n = wid & 3;     // 4 x 4 warps
    int row0 = blockIdx.x * 128;

    float acc[2][4][4];
#pragma unroll
    for (int mf = 0; mf < 2; mf++)
#pragma unroll
        for (int nf = 0; nf < 4; nf++)
#pragma unroll
            for (int q = 0; q < 4; q++) acc[mf][nf][q] = 0.0f;

    int aRow = warp_m * 32 + (lane & 15);        // + mf*16
    int aSw  = lane & 7;
    int kuHi = (lane >> 4);
    int bKrl = (lane & 7) + ((lane >> 3) & 1) * 8;
    int bNuL = (lane >> 4);

    k3_load(0, row0, T, W2h, dbase, dbase + K3_A_BYTES, tid);
    cp_commit();

    for (int j = 0; j < K3_CHUNKS; j++) {
        cp_wait0();
        __syncthreads();
        if (j + 1 < K3_CHUNKS) {
            uint32_t sN = dbase + ((j + 1) & 1) * K3_STAGE;
            k3_load(j + 1, row0, T, W2h, sN, sN + K3_A_BYTES, tid);
            cp_commit();
        }
        uint32_t sA = dbase + (j & 1) * K3_STAGE;
        uint32_t sB = sA + K3_A_BYTES;
#pragma unroll
        for (int kk = 0; kk < 8; kk++) {
            uint32_t a[2][4];
#pragma unroll
            for (int mf = 0; mf < 2; mf++) {
                int rowm = aRow + mf * 16;
                uint32_t ad = sA + rowm * 256 + (((kk * 2 + kuHi) ^ aSw) << 4);
                ld4(a[mf][0], a[mf][1], a[mf][2], a[mf][3], ad);
            }
#pragma unroll
            for (int np = 0; np < 2; np++) {
                int krow = kk * 16 + bKrl;
                int nu = warp_n * 4 + np * 2 + bNuL;
                uint32_t bd = sB + krow * 256 + (((nu ^ (krow & 7))) << 4);
                uint32_t b0, b1r, b2, b3;
                ld4t(b0, b1r, b2, b3, bd);
                int nf0 = np * 2, nf1 = nf0 + 1;
#pragma unroll
                for (int mf = 0; mf < 2; mf++) {
                    mma16(acc[mf][nf0][0], acc[mf][nf0][1], acc[mf][nf0][2], acc[mf][nf0][3],
                          a[mf][0], a[mf][1], a[mf][2], a[mf][3], b0, b1r);
                    mma16(acc[mf][nf1][0], acc[mf][nf1][1], acc[mf][nf1][2], acc[mf][nf1][3],
                          a[mf][0], a[mf][1], a[mf][2], a[mf][3], b2, b3);
                }
            }
        }
    }

    // epilogue: residual + mask (fp32 out)
#pragma unroll
    for (int mf = 0; mf < 2; mf++) {
        int rr = row0 + warp_m * 32 + mf * 16 + gid;
        float m0 = (__ldg(&z[rr])     > -1) ? 0.1f : 0.0f;
        float m8 = (__ldg(&z[rr + 8]) > -1) ? 0.1f : 0.0f;
#pragma unroll
        for (int nf = 0; nf < 4; nf++) {
            int cc = warp_n * 32 + nf * 8 + tig * 2;
            float ba = __ldg(&b2[cc]), bb = __ldg(&b2[cc + 1]);
            float2 h0 = *(const float2*)&h[(size_t)rr * F + cc];
            float2 h8 = *(const float2*)&h[(size_t)(rr + 8) * F + cc];
            float o0 = h0.x + m0 * (acc[mf][nf][0] + ba);
            float o1 = h0.y + m0 * (acc[mf][nf][1] + bb);
            float o2 = h8.x + m8 * (acc[mf][nf][2] + ba);
            float o3 = h8.y + m8 * (acc[mf][nf][3] + bb);
            *(float2*)&out[(size_t)rr * F + cc]       = make_float2(o0, o1);
            *(float2*)&out[(size_t)(rr + 8) * F + cc] = make_float2(o2, o3);
        }
    }
}

extern "C" void kernel_launch(void* const* d_in, const int* in_sizes, int n_in,
                              void* d_out, int out_size)
{
    const int*   z    = (const int*)d_in[0];
    const float* r    = (const float*)d_in[1];
    const float* h    = (const float*)d_in[2];
    const float* dist = (const float*)d_in[3];
    const float* wids = (const float*)d_in[4];
    const float* W1   = (const float*)d_in[5];
    const float* b1   = (const float*)d_in[6];
    const float* W2   = (const float*)d_in[7];
    const float* b2   = (const float*)d_in[8];

    __half *Uh, *Th, *hh, *W1h, *W2h;
    cudaGetSymbolAddress((void**)&Uh,  g_Uh);
    cudaGetSymbolAddress((void**)&Th,  g_Th);
    cudaGetSymbolAddress((void**)&hh,  g_hh);
    cudaGetSymbolAddress((void**)&W1h, g_W1h);
    cudaGetSymbolAddress((void**)&W2h, g_W2h);

    int nz = in_sizes[0], nr = in_sizes[1], nh = in_sizes[2];
    int nmol = nh / (MA * F);            // 512
    int rows = nmol * MA;                // 32768

    float* out   = (float*)d_out;
    float* out_h = out;
    int ncopy = 0;
    float *oz = nullptr, *orr = nullptr;
    if (out_size == nz + nr + nh) {
        ncopy = nz + nr;
        oz  = out;
        orr = out + nz;
        out_h = out + nz + nr;
    }

    int ncvt4 = (nh + DIN * HID + HID * F) / 4;
    int ntot  = ncopy + ncvt4;
    kprep<<<(ntot + 255) / 256, 256>>>(z, r, h, W1, W2, oz, orr, hh, W1h, W2h,
                                       nz, nr, nh, ncopy);

    k1_tc<<<nmol, 256>>>(z, r, dist, wids, hh, Uh);

    cudaFuncSetAttribute(k2_tc, cudaFuncAttributeMaxDynamicSharedMemorySize, K2_DYN);
    k2_tc<<<dim3(HID / 256, rows / 128), 512, K2_DYN>>>(hh, Uh, W1h, b1, Th);

    cudaFuncSetAttribute(k3_tc, cudaFuncAttributeMaxDynamicSharedMemorySize, K3_DYN);
    k3_tc<<<rows / 128, 512, K3_DYN>>>(Th, W2h, b2, h, z, out_h);
}